// round 1
// baseline (speedup 1.0000x reference)
#include <cuda_runtime.h>
#include <mma.h>

using namespace nvcuda;

// Problem constants
#define D_DIM     256
#define ROWS_TOT  (8 * 4096)      // B*S = 32768
#define N_INTENT  512
#define N_SLOT    1024

// Tiling
#define TILE_M    64              // rows per CTA
#define NC        32              // label chunk
#define XLD       260             // padded ld for Xs / Ws (multiple of 4 floats)
#define PLD       36              // padded ld for P chunk
#define THREADS   256             // 8 warps

// Shared layout (floats):
//   Xs  [TILE_M][XLD]   = 64*260
//   Ws  [NC][XLD]       = 32*260
//   Ps  [TILE_M][PLD]   = 64*36
//   den [TILE_M]
#define SMEM_FLOATS (TILE_M*XLD + NC*XLD + TILE_M*PLD + TILE_M)

__global__ void __launch_bounds__(THREADS, 2)
label_attn_kernel(const float* __restrict__ x_intent,
                  const float* __restrict__ x_slot,
                  const float* __restrict__ w_intent,
                  const float* __restrict__ w_slot,
                  float* __restrict__ out)
{
    extern __shared__ float smem[];
    float* Xs  = smem;                         // [64][260]
    float* Ws  = Xs + TILE_M * XLD;            // [32][260]
    float* Ps  = Ws + NC * XLD;                // [64][36]
    float* den = Ps + TILE_M * PLD;            // [64]

    const int branch = blockIdx.y;             // 0 = intent, 1 = slot
    const float* __restrict__ Xin  = branch ? x_slot : x_intent;
    const float* __restrict__ Wlab = branch ? w_slot : w_intent;
    float* __restrict__ Oout = out + (branch ? (size_t)ROWS_TOT * D_DIM : 0);
    const int Nlab = branch ? N_SLOT : N_INTENT;

    const int tid  = threadIdx.x;
    const int warp = tid >> 5;
    const int wm   = warp & 3;    // row-tile index (0..3): rows wm*16..+15
    const int wd   = warp >> 2;   // 0..1: GEMM1 n-subtile / GEMM2 col half
    const long row0 = (long)blockIdx.x * TILE_M;

    // ---- load X tile [64][256] into shared, tf32-rounded ----
    for (int i = tid; i < TILE_M * D_DIM; i += THREADS) {
        int r = i >> 8;            // /256
        int c = i & 255;
        Xs[r * XLD + c] = wmma::__float_to_tf32(Xin[(row0 + r) * D_DIM + c]);
    }
    if (tid < TILE_M) den[tid] = 0.0f;

    // ---- persistent output accumulators: warp owns rows wm*16..+15, cols wd*128..+127 ----
    wmma::fragment<wmma::accumulator, 16, 16, 8, float> acc[8];
#pragma unroll
    for (int t = 0; t < 8; t++) wmma::fill_fragment(acc[t], 0.0f);

    for (int n0 = 0; n0 < Nlab; n0 += NC) {
        __syncthreads();  // previous chunk's GEMM2 done (Ws/Ps reusable); Xs ready on iter 0

        // ---- stage W chunk [NC][256] to shared, tf32-rounded ----
        for (int i = tid; i < NC * D_DIM; i += THREADS) {
            int r = i >> 8;
            int c = i & 255;
            Ws[r * XLD + c] = wmma::__float_to_tf32(Wlab[(size_t)(n0 + r) * D_DIM + c]);
        }
        __syncthreads();

        // ---- GEMM1: S[64][32] = X[64][256] * Wchunk^T ; warp -> tile (wm, wd) 16x16 ----
        {
            wmma::fragment<wmma::accumulator, 16, 16, 8, float> sAcc;
            wmma::fill_fragment(sAcc, 0.0f);
            wmma::fragment<wmma::matrix_a, 16, 16, 8, wmma::precision::tf32, wmma::row_major> aF;
            wmma::fragment<wmma::matrix_b, 16, 16, 8, wmma::precision::tf32, wmma::col_major> bF;
            const float* Abase = Xs + (wm * 16) * XLD;
            const float* Bbase = Ws + (wd * 16) * XLD;   // B col-major: elem(k,n) = Ws[n][k]
#pragma unroll
            for (int k = 0; k < D_DIM; k += 8) {
                wmma::load_matrix_sync(aF, Abase + k, XLD);
                wmma::load_matrix_sync(bF, Bbase + k, XLD);
                wmma::mma_sync(sAcc, aF, bF, sAcc);
            }
            wmma::store_matrix_sync(Ps + (wm * 16) * PLD + wd * 16, sAcc, PLD,
                                    wmma::mem_row_major);
        }
        __syncthreads();

        // ---- exp + denominator; logits |s| ~ 2 so no max-subtraction needed ----
        {
            int r  = tid >> 2;            // 0..63
            int c0 = (tid & 3) * 8;       // 4 threads per row, 8 cols each
            float* p = Ps + r * PLD + c0;
            float partial = 0.0f;
#pragma unroll
            for (int j = 0; j < 8; j++) {
                float e = __expf(p[j]);
                partial += e;
                p[j] = wmma::__float_to_tf32(e);
            }
            partial += __shfl_xor_sync(0xffffffff, partial, 1);
            partial += __shfl_xor_sync(0xffffffff, partial, 2);
            if ((tid & 3) == 0) den[r] += partial;   // unique writer per (r, chunk)
        }
        __syncthreads();

        // ---- GEMM2: Acc[64][256] += P[64][32] * Wchunk[32][256] ----
        {
            wmma::fragment<wmma::matrix_a, 16, 16, 8, wmma::precision::tf32, wmma::row_major> aF;
            wmma::fragment<wmma::matrix_b, 16, 16, 8, wmma::precision::tf32, wmma::row_major> bF;
            const float* Abase = Ps + (wm * 16) * PLD;
#pragma unroll
            for (int k = 0; k < NC; k += 8) {
                wmma::load_matrix_sync(aF, Abase + k, PLD);
                const float* Bk = Ws + k * XLD + wd * 128;
#pragma unroll
                for (int t = 0; t < 8; t++) {
                    wmma::load_matrix_sync(bF, Bk + t * 16, XLD);
                    wmma::mma_sync(acc[t], aF, bF, acc[t]);
                }
            }
        }
    }
    __syncthreads();

    if (tid < TILE_M) den[tid] = 1.0f / den[tid];

    // ---- stage Acc to shared (reuse Xs region), then scaled coalesced store ----
    float* Os = Xs;
#pragma unroll
    for (int t = 0; t < 8; t++) {
        wmma::store_matrix_sync(Os + (wm * 16) * XLD + wd * 128 + t * 16, acc[t], XLD,
                                wmma::mem_row_major);
    }
    __syncthreads();

    for (int i = tid; i < TILE_M * D_DIM; i += THREADS) {
        int r = i >> 8;
        int c = i & 255;
        Oout[(row0 + r) * D_DIM + c] = Os[r * XLD + c] * den[r];
    }
}

extern "C" void kernel_launch(void* const* d_in, const int* in_sizes, int n_in,
                              void* d_out, int out_size)
{
    const float* x_intent = (const float*)d_in[0];   // [8,4096,256] f32
    const float* x_slot   = (const float*)d_in[1];   // [8,4096,256] f32
    // d_in[2] = mask (unused)
    const float* w_intent = (const float*)d_in[3];   // [512,256]  f32
    const float* w_slot   = (const float*)d_in[4];   // [1024,256] f32
    float* out = (float*)d_out;                      // intent_res then slot_res

    const size_t shmem = SMEM_FLOATS * sizeof(float);
    cudaFuncSetAttribute(label_attn_kernel,
                         cudaFuncAttributeMaxDynamicSharedMemorySize, (int)shmem);

    dim3 grid(ROWS_TOT / TILE_M, 2, 1);   // 512 row-tiles x {intent, slot}
    label_attn_kernel<<<grid, THREADS, shmem>>>(x_intent, x_slot, w_intent, w_slot, out);
}

// round 3
// speedup vs baseline: 4.6197x; 4.6197x over previous
#include <cuda_runtime.h>
#include <cuda_fp16.h>
#include <cstdint>

#define D_DIM    256
#define ROWS     32768
#define TILE_M   64
#define NC       32
#define THREADS  256

// fp16 label tables (converted by prepass): intent [512*256], slot [1024*256]
__device__ __half Wh[(512 + 1024) * 256];

// smem byte offsets
#define XS   0               // X tile: 64 rows * 512B (fp16, swizzled)
#define WS   32768           // 2 x 16384 W chunk double buffer
#define PS   65536           // P: 64 rows * 80B (padded)
#define DEN  70656           // 2 * 64 floats
#define SMEM_BYTES 71168

static __device__ __forceinline__ uint32_t smem_u32(const void* p) {
    uint32_t a;
    asm("{ .reg .u64 t; cvta.to.shared.u64 t, %1; cvt.u32.u64 %0, t; }" : "=r"(a) : "l"(p));
    return a;
}
static __device__ __forceinline__ uint32_t pack2(float lo, float hi) {
    __half2 h = __floats2half2_rn(lo, hi);
    return reinterpret_cast<uint32_t&>(h);
}

#define LDSM_X4(r0, r1, r2, r3, p) \
    asm volatile("ldmatrix.sync.aligned.m8n8.x4.shared.b16 {%0,%1,%2,%3}, [%4];" \
        : "=r"(r0), "=r"(r1), "=r"(r2), "=r"(r3) : "r"(p))
#define LDSM_X4T(r0, r1, r2, r3, p) \
    asm volatile("ldmatrix.sync.aligned.m8n8.x4.trans.shared.b16 {%0,%1,%2,%3}, [%4];" \
        : "=r"(r0), "=r"(r1), "=r"(r2), "=r"(r3) : "r"(p))
#define MMA(C, a0, a1, a2, a3, b0, b1) \
    asm volatile("mma.sync.aligned.m16n8k16.row.col.f32.f16.f16.f32 " \
        "{%0,%1,%2,%3}, {%4,%5,%6,%7}, {%8,%9}, {%0,%1,%2,%3};" \
        : "+f"((C)[0]), "+f"((C)[1]), "+f"((C)[2]), "+f"((C)[3]) \
        : "r"(a0), "r"(a1), "r"(a2), "r"(a3), "r"(b0), "r"(b1))
#define CP16(dst, src) \
    asm volatile("cp.async.cg.shared.global [%0], [%1], 16;" :: "r"(dst), "l"(src))
#define CP_COMMIT() asm volatile("cp.async.commit_group;" ::: "memory")
#define CP_WAIT1() asm volatile("cp.async.wait_group 1;" ::: "memory")
#define CP_WAIT0() asm volatile("cp.async.wait_group 0;" ::: "memory")

// ---- prepass: convert fp32 W tables to fp16 global
__global__ void wcvt_kernel(const float* __restrict__ wi, const float* __restrict__ ws) {
    int i = blockIdx.x * blockDim.x + threadIdx.x;   // one float4 each
    __half2* dst = (__half2*)Wh;
    if (i < 32768) {                                  // intent: 512*256/4
        float4 v = __ldg((const float4*)wi + i);
        dst[i * 2]     = __floats2half2_rn(v.x, v.y);
        dst[i * 2 + 1] = __floats2half2_rn(v.z, v.w);
    }
    if (i < 65536) {                                  // slot: 1024*256/4
        float4 v = __ldg((const float4*)ws + i);
        __half2* d2 = (__half2*)(Wh + 512 * 256);
        d2[i * 2]     = __floats2half2_rn(v.x, v.y);
        d2[i * 2 + 1] = __floats2half2_rn(v.z, v.w);
    }
}

__global__ void __launch_bounds__(THREADS, 2)
label_attn_fp16(const float* __restrict__ x_intent,
                const float* __restrict__ x_slot,
                float* __restrict__ out)
{
    extern __shared__ char smem[];
    const uint32_t sb = smem_u32(smem);
    const int tid = threadIdx.x, lane = tid & 31, warp = tid >> 5;
    const int wm = warp >> 1, wh = warp & 1;

    int bid = blockIdx.x, branch, tile;
    if (bid < 512) { branch = 1; tile = bid; } else { branch = 0; tile = bid - 512; }
    const float* __restrict__ Xin = branch ? x_slot : x_intent;
    const __half* __restrict__ Wg = Wh + (branch ? 512 * 256 : 0);
    float* __restrict__ Oout = out + (size_t)branch * ROWS * D_DIM;
    const int nch = branch ? 32 : 16;
    const long row0 = (long)tile * TILE_M;

    // ---- X tile: fp32 gmem -> fp16 swizzled smem (once)
    {
        const float4* X4 = (const float4*)(Xin + row0 * D_DIM);
        for (int i = tid; i < TILE_M * 64; i += THREADS) {
            int r = i >> 6, c4 = i & 63;          // c4: 4-float group
            float4 v = __ldg(&X4[r * 64 + c4]);
            uint32_t h0 = pack2(v.x, v.y), h1 = pack2(v.z, v.w);
            int ck = c4 >> 1;                     // 16B chunk index (0..31)
            uint32_t dst = sb + XS + r * 512 + ((ck ^ (r & 7)) << 4) + ((c4 & 1) << 3);
            asm volatile("st.shared.v2.b32 [%0], {%1, %2};" :: "r"(dst), "r"(h0), "r"(h1) : "memory");
        }
    }

    // ---- W chunk cp.async loader (fp16 gmem -> swizzled smem buffer)
    auto issue_w = [&](int chunk, int b) {
        const __half* src0 = Wg + (size_t)chunk * NC * 256;
        for (int i = tid; i < 1024; i += THREADS) {      // 32 rows x 32 chunks of 16B
            int r = i >> 5, c = i & 31;
            uint32_t dst = sb + WS + (b << 14) + r * 512 + ((c ^ (r & 7)) << 4);
            CP16(dst, src0 + r * 256 + c * 8);
        }
        CP_COMMIT();
    };
    issue_w(0, 0);
    issue_w(1, 1);

    // ---- per-thread precomputed addressing
    const int lo7 = lane & 7, hi = lane >> 4, g8 = ((lane >> 3) & 1) << 3;
    const int gg = lane >> 2, tt = lane & 3;
    const uint32_t xa_row = sb + XS + (wm * 16 + lo7 + g8) * 512;
    const int xa_sw = (wm * 16 + lo7 + g8) & 7;
    const uint32_t wb_row = (wh * 16 + lo7 + g8) * 512;      // GEMM1 B rows = labels
    const int wb_sw = (wh * 16 + lo7 + g8) & 7;
    const uint32_t pa_row = sb + PS + (wm * 16 + lo7 + g8) * 80;
    const uint32_t b2_row = (lo7 + g8) * 512;                // GEMM2 B rows = labels (k)
    const int b2_sw = lo7;
    const uint32_t ps_st = sb + PS + (wm * 16 + gg) * 80 + (wh * 16 + 2 * tt) * 2;

    float O[64];
#pragma unroll
    for (int j = 0; j < 64; j++) O[j] = 0.0f;
    float den0 = 0.0f, den1 = 0.0f;

    for (int i = 0; i < nch; i++) {
        const uint32_t Wbase = sb + WS + ((i & 1) << 14);
        if (i == nch - 1) CP_WAIT0(); else CP_WAIT1();
        __syncthreads();

        // ---- GEMM1: S[m16 x n16] = X[m16 x 256] * Wchunk^T (warp's h-half)
        float S[8];
#pragma unroll
        for (int j = 0; j < 8; j++) S[j] = 0.0f;
#pragma unroll
        for (int kk = 0; kk < 16; kk++) {
            uint32_t a0, a1, a2, a3, b0, b1, b2, b3;
            LDSM_X4(a0, a1, a2, a3, xa_row + (((2 * kk + hi) ^ xa_sw) << 4));
            LDSM_X4(b0, b1, b2, b3, Wbase + wb_row + (((2 * kk + hi) ^ wb_sw) << 4));
            MMA(S,     a0, a1, a2, a3, b0, b2);
            MMA(S + 4, a0, a1, a2, a3, b1, b3);
        }

        // ---- softmax piece: exp, accumulate row denominators, stage P to smem (fp16)
        float e0 = __expf(S[0]), e1 = __expf(S[1]), e2 = __expf(S[2]), e3 = __expf(S[3]);
        float e4 = __expf(S[4]), e5 = __expf(S[5]), e6 = __expf(S[6]), e7 = __expf(S[7]);
        den0 += e0 + e1 + e4 + e5;
        den1 += e2 + e3 + e6 + e7;
        {
            uint32_t p0 = pack2(e0, e1), p1 = pack2(e2, e3);
            uint32_t p2 = pack2(e4, e5), p3 = pack2(e6, e7);
            asm volatile("st.shared.b32 [%0], %1;" :: "r"(ps_st),       "r"(p0) : "memory");
            asm volatile("st.shared.b32 [%0], %1;" :: "r"(ps_st + 640), "r"(p1) : "memory");
            asm volatile("st.shared.b32 [%0], %1;" :: "r"(ps_st + 16),  "r"(p2) : "memory");
            asm volatile("st.shared.b32 [%0], %1;" :: "r"(ps_st + 656), "r"(p3) : "memory");
        }
        __syncthreads();

        // ---- GEMM2: O[m16 x n128(half)] += P[m16 x 32] * Wchunk[32 x 256]
#pragma unroll
        for (int ks = 0; ks < 2; ks++) {
            uint32_t a0, a1, a2, a3;
            LDSM_X4(a0, a1, a2, a3, pa_row + ((2 * ks + hi) << 4));
            const uint32_t brow = Wbase + (ks << 13) + b2_row;
#pragma unroll
            for (int nt = 0; nt < 8; nt++) {
                uint32_t r0, r1, r2, r3;
                int nc_ = wh * 16 + 2 * nt + hi;
                LDSM_X4T(r0, r1, r2, r3, brow + ((nc_ ^ b2_sw) << 4));
                MMA(O + nt * 8,     a0, a1, a2, a3, r0, r1);
                MMA(O + nt * 8 + 4, a0, a1, a2, a3, r2, r3);
            }
        }
        __syncthreads();

        if (i + 2 < nch) issue_w(i + 2, i & 1);
    }

    // ---- finalize denominators (reduce quad lanes, then the two h-halves via smem)
    den0 += __shfl_xor_sync(0xffffffff, den0, 1);
    den0 += __shfl_xor_sync(0xffffffff, den0, 2);
    den1 += __shfl_xor_sync(0xffffffff, den1, 1);
    den1 += __shfl_xor_sync(0xffffffff, den1, 2);
    float* dsm = (float*)(smem + DEN);
    if (tt == 0) {
        dsm[wh * 64 + wm * 16 + gg]     = den0;
        dsm[wh * 64 + wm * 16 + gg + 8] = den1;
    }
    __syncthreads();
    const float inv0 = 1.0f / (dsm[wm * 16 + gg]     + dsm[64 + wm * 16 + gg]);
    const float inv1 = 1.0f / (dsm[wm * 16 + gg + 8] + dsm[64 + wm * 16 + gg + 8]);

    // ---- scaled store (C-frag direct: float2 per row/tile)
    {
        const long r_a = row0 + wm * 16 + gg, r_b = r_a + 8;
        const int cbase = wh * 128 + 2 * tt;
#pragma unroll
        for (int nt = 0; nt < 8; nt++) {
            int c0 = cbase + nt * 16, c1 = c0 + 8;
            *(float2*)&Oout[r_a * 256 + c0] = make_float2(O[nt * 8]     * inv0, O[nt * 8 + 1] * inv0);
            *(float2*)&Oout[r_b * 256 + c0] = make_float2(O[nt * 8 + 2] * inv1, O[nt * 8 + 3] * inv1);
            *(float2*)&Oout[r_a * 256 + c1] = make_float2(O[nt * 8 + 4] * inv0, O[nt * 8 + 5] * inv0);
            *(float2*)&Oout[r_b * 256 + c1] = make_float2(O[nt * 8 + 6] * inv1, O[nt * 8 + 7] * inv1);
        }
    }
}

extern "C" void kernel_launch(void* const* d_in, const int* in_sizes, int n_in,
                              void* d_out, int out_size)
{
    const float* x_intent = (const float*)d_in[0];
    const float* x_slot   = (const float*)d_in[1];
    // d_in[2] = mask (unused)
    const float* w_intent = (const float*)d_in[3];
    const float* w_slot   = (const float*)d_in[4];
    float* out = (float*)d_out;

    wcvt_kernel<<<256, 256>>>(w_intent, w_slot);

    cudaFuncSetAttribute(label_attn_fp16,
                         cudaFuncAttributeMaxDynamicSharedMemorySize, SMEM_BYTES);
    label_attn_fp16<<<1024, THREADS, SMEM_BYTES>>>(x_intent, x_slot, out);
}